// round 16
// baseline (speedup 1.0000x reference)
#include <cuda_runtime.h>
#include <cuda_fp16.h>
#include <math.h>
#include <stdint.h>

// Problem constants
#define Bn 4
#define Sn 1024
#define Tn 4096          // Bn*Sn tokens
#define Hn 512
#define En 8
#define Fn 2048
#define NBUCK 32         // En*Bn  (expert, batch) buckets
#define CAPn 1024        // max tokens per bucket = Sn

// ---------------- scratch (__device__ globals; no allocation) ----------------
__device__ __half g_xh  [(size_t)Tn*Hn];
__device__ __half g_Kh  [(size_t)En*Tn*Hn];
__device__ __half g_Vth [(size_t)En*Hn*Tn];          // V TRANSPOSED [e][h][t]
__device__ __half g_qh  [(size_t)NBUCK*CAPn*Hn];
__device__ __half g_h1h [(size_t)NBUCK*CAPn*Fn];
__device__ __half g_atth[(size_t)NBUCK*CAPn*Sn];     // UNNORMALIZED exp(scores) fp16
__device__ __half g_ah  [(size_t)NBUCK*CAPn*Hn];
__device__ __half g_qwT[(size_t)En*Hn*Hn];
__device__ __half g_kwT[(size_t)En*Hn*Hn];
__device__ __half g_vwT[(size_t)En*Hn*Hn];
__device__ __half g_owT[(size_t)En*Hn*Hn];
__device__ __half g_f1T[(size_t)En*Fn*Hn];
__device__ __half g_f2T[(size_t)En*Hn*Fn];
__device__ float g_rowsum[(size_t)NBUCK*CAPn];       // softmax denominators
__device__ float g_h2[(size_t)NBUCK*CAPn*Hn];
__device__ int   g_cnt[NBUCK];
__device__ int   g_tok[NBUCK*CAPn];
__device__ float g_wt [NBUCK*CAPn];
__device__ float g_imp[En];

__device__ __forceinline__ unsigned int f22u(float a, float b) {
    __half2 h = __floats2half2_rn(a, b);
    return *(unsigned int*)&h;
}
__device__ __forceinline__ uint32_t smem_u32(const void* p) {
    uint32_t a;
    asm("{ .reg .u64 t; cvta.to.shared.u64 t, %1; cvt.u32.u64 %0, t; }" : "=r"(a) : "l"(p));
    return a;
}

// ---------------- small kernels ----------------
__global__ void reset_kernel() {
    int i = threadIdx.x;   // 1 block, 32 threads: only router prerequisites
    if (i < NBUCK) g_cnt[i] = 0;
    if (i < En)    g_imp[i] = 0.f;
}

__global__ void zero_kernel(float* __restrict__ out, int n) {
    int i = blockIdx.x * blockDim.x + threadIdx.x;
    if (i < n) out[i] = 0.f;
}

__global__ void halve_kernel(const float* __restrict__ src, __half* __restrict__ dst, int n) {
    int i = (blockIdx.x * blockDim.x + threadIdx.x) * 4;
    if (i < n) {
        float4 v = *(const float4*)(src + i);
        uint2 o = make_uint2(f22u(v.x, v.y), f22u(v.z, v.w));
        *(uint2*)(dst + i) = o;
    }
}

// fp32 [E][R][C] -> fp16 [E][C][R]
__global__ void transpose_h_kernel(const float* __restrict__ in, __half* __restrict__ out,
                                   int R, int C)
{
    __shared__ float t[32][33];
    int e = blockIdx.z;
    const float* src = in + (size_t)e * R * C;
    __half* dst = out + (size_t)e * R * C;
    int c0 = blockIdx.x * 32, r0 = blockIdx.y * 32;
    int x = threadIdx.x, y = threadIdx.y;   // (32, 8)
#pragma unroll
    for (int i = 0; i < 32; i += 8)
        t[y + i][x] = src[(size_t)(r0 + y + i) * C + c0 + x];
    __syncthreads();
#pragma unroll
    for (int i = 0; i < 32; i += 8)
        dst[(size_t)(c0 + y + i) * R + r0 + x] = __float2half_rn(t[x][y + i]);
}

// Router: one warp per token. Exact fp32.
__global__ void router_kernel(const float* __restrict__ x,
                              const float* __restrict__ Wg,
                              const float* __restrict__ bg)
{
    int warp = (blockIdx.x * blockDim.x + threadIdx.x) >> 5;
    int lane = threadIdx.x & 31;
    if (warp >= Tn) return;
    const int t = warp;

    float acc[En];
#pragma unroll
    for (int e = 0; e < En; e++) acc[e] = 0.f;

    for (int h = lane; h < Hn; h += 32) {
        float xv = x[(size_t)t * Hn + h];
        float4 w0 = *(const float4*)(Wg + (size_t)h * En);
        float4 w1 = *(const float4*)(Wg + (size_t)h * En + 4);
        acc[0] += xv * w0.x; acc[1] += xv * w0.y; acc[2] += xv * w0.z; acc[3] += xv * w0.w;
        acc[4] += xv * w1.x; acc[5] += xv * w1.y; acc[6] += xv * w1.z; acc[7] += xv * w1.w;
    }
#pragma unroll
    for (int off = 16; off > 0; off >>= 1) {
#pragma unroll
        for (int e = 0; e < En; e++)
            acc[e] += __shfl_xor_sync(0xffffffffu, acc[e], off);
    }
    if (lane != 0) return;

    float p[En];
    float m = -1e30f;
#pragma unroll
    for (int e = 0; e < En; e++) { p[e] = acc[e] + bg[e]; m = fmaxf(m, p[e]); }
    float s = 0.f;
#pragma unroll
    for (int e = 0; e < En; e++) { p[e] = expf(p[e] - m); s += p[e]; }
    float inv = 1.0f / s;
#pragma unroll
    for (int e = 0; e < En; e++) { p[e] *= inv; atomicAdd(&g_imp[e], p[e]); }

    int i1 = 0;
#pragma unroll
    for (int e = 1; e < En; e++) if (p[e] > p[i1]) i1 = e;
    int i2 = (i1 == 0) ? 1 : 0;
#pragma unroll
    for (int e = 0; e < En; e++) if (e != i1 && p[e] > p[i2]) i2 = e;

    float denom = p[i1] + p[i2];
    int b = t >> 10;
    int bk1 = i1 * Bn + b;
    int pos1 = atomicAdd(&g_cnt[bk1], 1);
    g_tok[bk1 * CAPn + pos1] = t;
    g_wt [bk1 * CAPn + pos1] = p[i1] / denom;
    int bk2 = i2 * Bn + b;
    int pos2 = atomicAdd(&g_cnt[bk2], 1);
    g_tok[bk2 * CAPn + pos2] = t;
    g_wt [bk2 * CAPn + pos2] = p[i2] / denom;
}

__global__ void finalize_kernel(float* __restrict__ out, int out_size)
{
    if (threadIdx.x == 0 && out_size > Tn * Hn) {
        float loss = 0.f;
        for (int e = 0; e < En; e++) {
            int a = 0;
            for (int b = 0; b < Bn; b++) a += g_cnt[e * Bn + b];
            loss += ((float)a / (float)Tn) * (g_imp[e] / (float)Tn);
        }
        out[Tn * Hn] = (float)En * loss;
    }
}

// ---------------- fp16 mma GEMM: 128x128 tile, 8 warps 64x32, 3-stage cp.async + ldmatrix ----------------
enum { KK = 0, KV = 1, KQ = 2, KF1 = 3, KF2 = 4, KSC = 5, KPV = 6, KO = 7 };

__device__ __forceinline__ void mma_f16_16x8x16(float* c, const unsigned int* a, const unsigned int* b) {
    asm volatile(
        "mma.sync.aligned.m16n8k16.row.col.f32.f16.f16.f32 "
        "{%0,%1,%2,%3}, {%4,%5,%6,%7}, {%8,%9}, {%0,%1,%2,%3};"
        : "+f"(c[0]), "+f"(c[1]), "+f"(c[2]), "+f"(c[3])
        : "r"(a[0]), "r"(a[1]), "r"(a[2]), "r"(a[3]), "r"(b[0]), "r"(b[1]));
}
#define LDSM4(r0, r1, r2, r3, addr) \
    asm volatile("ldmatrix.sync.aligned.m8n8.x4.shared.b16 {%0,%1,%2,%3}, [%4];" \
                 : "=r"(r0), "=r"(r1), "=r"(r2), "=r"(r3) : "r"(addr))
#define CP16(dst, src, sz) \
    asm volatile("cp.async.cg.shared.global [%0], [%1], 16, %2;" :: "r"(dst), "l"(src), "r"(sz) : "memory")
#define CP_COMMIT() asm volatile("cp.async.commit_group;" ::: "memory")
#define CP_WAIT(n)  asm volatile("cp.async.wait_group %0;" :: "n"(n) : "memory")

#define STR 24            // halfs per smem row (48 B) -> conflict-free LDSM & cp.async
#define TILEH (128*STR)   // halfs per tile (6 KB)

template <int KIND>
__global__ __launch_bounds__(256, 2)
void gemm_kernel(const float* __restrict__ bias, float* __restrict__ outp)
{
    constexpr bool BUCKET = (KIND != KK && KIND != KV);
    constexpr int  KDIM = (KIND == KF2) ? Fn : (KIND == KPV ? Sn : Hn);
    constexpr int  NC   = KDIM / 16;

    const int tid  = threadIdx.x;
    const int wid  = tid >> 5;
    const int lane = tid & 31;
    const int z = blockIdx.z;
    int e, bb = 0, M;
    if (BUCKET) {
        e = z >> 2; bb = z & 3;
        M = g_cnt[z];
        if ((int)(blockIdx.x * 128) >= M) return;
    } else {
        e = z; M = Tn;
    }

    const int row0 = blockIdx.x * 128;
    const int col0 = blockIdx.y * 128;

    const int lrow = tid & 127;
    const int s    = tid >> 7;
    const int grow = row0 + lrow;
    const bool aval = BUCKET ? (grow < M) : true;
    const unsigned avsz = aval ? 16u : 0u;

    const __half* aPtr = nullptr;
    if (aval) {
        if      (KIND == KK || KIND == KV)   aPtr = g_xh + (size_t)grow * Hn;
        else if (KIND == KQ || KIND == KF1)  aPtr = g_xh + (size_t)g_tok[z * CAPn + grow] * Hn;
        else if (KIND == KF2)                aPtr = g_h1h  + ((size_t)z * CAPn + grow) * Fn;
        else if (KIND == KSC)                aPtr = g_qh   + ((size_t)z * CAPn + grow) * Hn;
        else if (KIND == KPV)                aPtr = g_atth + ((size_t)z * CAPn + grow) * Sn;
        else                                 aPtr = g_ah   + ((size_t)z * CAPn + grow) * Hn;  // KO
        aPtr += s * 8;
    }
    const __half* bPtr;
    if      (KIND == KK)  bPtr = g_kwT + ((size_t)e * Hn + col0 + lrow) * Hn;
    else if (KIND == KV)  bPtr = g_vwT + ((size_t)e * Hn + col0 + lrow) * Hn;
    else if (KIND == KQ)  bPtr = g_qwT + ((size_t)e * Hn + col0 + lrow) * Hn;
    else if (KIND == KO)  bPtr = g_owT + ((size_t)e * Hn + col0 + lrow) * Hn;
    else if (KIND == KF1) bPtr = g_f1T + ((size_t)e * Fn + col0 + lrow) * Hn;
    else if (KIND == KF2) bPtr = g_f2T + ((size_t)e * Hn + col0 + lrow) * Fn;
    else if (KIND == KSC) bPtr = g_Kh  + ((size_t)e * Tn + (size_t)bb * Sn + col0 + lrow) * Hn;
    else                  bPtr = g_Vth + ((size_t)e * Hn + col0 + lrow) * Tn + bb * Sn;  // KPV
    bPtr += s * 8;

    __shared__ __align__(16) __half smh[6 * TILEH];   // 3 stages x (A,B) = 36 KB
    const uint32_t sb = smem_u32(smh);
    const uint32_t aDst = sb + (lrow * STR + s * 8) * 2;
    const uint32_t bDst = sb + 3 * TILEH * 2 + (lrow * STR + s * 8) * 2;

    float acc[4][4][4];
#pragma unroll
    for (int i = 0; i < 4; i++)
#pragma unroll
        for (int j = 0; j < 4; j++)
#pragma unroll
            for (int k = 0; k < 4; k++) acc[i][j][k] = 0.f;

    const int wm  = (wid >> 2) * 64;
    const int wn  = (wid & 3) * 32;
    const int grp = lane >> 2;
    const int tg  = lane & 3;

    const int arow = wm + (lane & 7) + ((lane >> 3) & 1) * 8;
    const int agr  = lane >> 4;
    const uint32_t aLd0 = sb + (arow * STR + agr * 8) * 2;
    const int brow = wn + (lane & 7) + ((lane >= 16) ? 8 : 0);
    const int bgr  = (lane >> 3) & 1;
    const uint32_t bLd0 = sb + 3 * TILEH * 2 + (brow * STR + bgr * 8) * 2;

    auto issue = [&](int st, int c) {
        CP16(aDst + st * TILEH * 2, aPtr + c * 16, avsz);
        CP16(bDst + st * TILEH * 2, bPtr + c * 16, 16u);
        CP_COMMIT();
    };

    issue(0, 0);
    issue(1, 1);

    for (int c = 0; c < NC; c++) {
        if (c + 1 < NC) { CP_WAIT(1); } else { CP_WAIT(0); }
        __syncthreads();
        if (c + 2 < NC) issue((c + 2) % 3, c + 2);

        const uint32_t off = ((c % 3) * TILEH) * 2;
        unsigned int af[4][4], bf[4][2];
#pragma unroll
        for (int mt = 0; mt < 4; mt++)
            LDSM4(af[mt][0], af[mt][1], af[mt][2], af[mt][3], aLd0 + off + mt * 16 * STR * 2);
        {
            unsigned int r0, r1, r2, r3;
            LDSM4(r0, r1, r2, r3, bLd0 + off);
            bf[0][0] = r0; bf[0][1] = r1; bf[1][0] = r2; bf[1][1] = r3;
            LDSM4(r0, r1, r2, r3, bLd0 + off + 16 * STR * 2);
            bf[2][0] = r0; bf[2][1] = r1; bf[3][0] = r2; bf[3][1] = r3;
        }
#pragma unroll
        for (int mt = 0; mt < 4; mt++)
#pragma unroll
            for (int nt = 0; nt < 4; nt++)
                mma_f16_16x8x16(acc[mt][nt], af[mt], bf[nt]);
    }

    // ---------------- epilogue ----------------
#pragma unroll
    for (int mt = 0; mt < 4; mt++) {
#pragma unroll
        for (int half = 0; half < 2; half++) {
            const int r = row0 + wm + mt * 16 + grp + half * 8;

            if (KIND == KSC) {
                // fused softmax part 1: exp + row-sum accumulation (shuffles kept convergent)
                const float scl = 0.044194173824159216f;  // 1/sqrt(512)
                float ev[8];
                float psum = 0.f;
#pragma unroll
                for (int nt = 0; nt < 4; nt++) {
                    ev[nt*2]   = __expf(acc[mt][nt][half*2]   * scl);
                    ev[nt*2+1] = __expf(acc[mt][nt][half*2+1] * scl);
                    psum += ev[nt*2] + ev[nt*2+1];
                }
                psum += __shfl_xor_sync(0xffffffffu, psum, 1);
                psum += __shfl_xor_sync(0xffffffffu, psum, 2);
                if (r < M) {
                    __half* C = g_atth + ((size_t)z * CAPn + r) * Sn;
#pragma unroll
                    for (int nt = 0; nt < 4; nt++) {
                        const int c = col0 + wn + nt * 8 + tg * 2;
                        *(unsigned int*)(C + c) = f22u(ev[nt*2], ev[nt*2+1]);
                    }
                    if (tg == 0) atomicAdd(&g_rowsum[z * CAPn + r], psum);
                }
                continue;
            }

            if (BUCKET && r >= M) continue;

            if (KIND == KK) {
                __half* C = g_Kh + ((size_t)e * Tn + r) * Hn;
                const float* bp = bias + (size_t)e * Hn;
#pragma unroll
                for (int nt = 0; nt < 4; nt++) {
                    const int c = col0 + wn + nt * 8 + tg * 2;
                    float2 bv = *(const float2*)(bp + c);
                    *(unsigned int*)(C + c) = f22u(acc[mt][nt][half*2] + bv.x,
                                                   acc[mt][nt][half*2+1] + bv.y);
                }
            } else if (KIND == KV) {
                const float* bp = bias + (size_t)e * Hn;
                __half* Vb = g_Vth + (size_t)e * Hn * Tn + r;
#pragma unroll
                for (int nt = 0; nt < 4; nt++) {
                    const int c = col0 + wn + nt * 8 + tg * 2;
                    float2 bv = *(const float2*)(bp + c);
                    Vb[(size_t)c * Tn]       = __float2half_rn(acc[mt][nt][half*2]   + bv.x);
                    Vb[(size_t)(c + 1) * Tn] = __float2half_rn(acc[mt][nt][half*2+1] + bv.y);
                }
            } else if (KIND == KQ) {
                __half* C = g_qh + ((size_t)z * CAPn + r) * Hn;
                const float* bp = bias + (size_t)e * Hn;
#pragma unroll
                for (int nt = 0; nt < 4; nt++) {
                    const int c = col0 + wn + nt * 8 + tg * 2;
                    float2 bv = *(const float2*)(bp + c);
                    *(unsigned int*)(C + c) = f22u(acc[mt][nt][half*2] + bv.x,
                                                   acc[mt][nt][half*2+1] + bv.y);
                }
            } else if (KIND == KF1) {
                __half* C = g_h1h + ((size_t)z * CAPn + r) * Fn;
                const float* bp = bias + (size_t)e * Fn;
#pragma unroll
                for (int nt = 0; nt < 4; nt++) {
                    const int c = col0 + wn + nt * 8 + tg * 2;
                    float2 bv = *(const float2*)(bp + c);
                    float t0 = acc[mt][nt][half*2]   + bv.x;
                    float t1 = acc[mt][nt][half*2+1] + bv.y;
                    t0 = 0.5f * t0 * (1.0f + erff(t0 * 0.70710678118654752f));
                    t1 = 0.5f * t1 * (1.0f + erff(t1 * 0.70710678118654752f));
                    *(unsigned int*)(C + c) = f22u(t0, t1);
                }
            } else if (KIND == KF2) {
                float* C = g_h2 + ((size_t)z * CAPn + r) * Hn;
                const float* bp = bias + (size_t)e * Hn;
#pragma unroll
                for (int nt = 0; nt < 4; nt++) {
                    const int c = col0 + wn + nt * 8 + tg * 2;
                    float2 bv = *(const float2*)(bp + c);
                    float2 v = make_float2(acc[mt][nt][half*2]   + bv.x,
                                           acc[mt][nt][half*2+1] + bv.y);
                    *(float2*)(C + c) = v;
                }
            } else if (KIND == KPV) {
                // fused softmax part 2: scale by 1/rowsum
                const float invz = 1.0f / g_rowsum[z * CAPn + r];
                __half* C = g_ah + ((size_t)z * CAPn + r) * Hn;
#pragma unroll
                for (int nt = 0; nt < 4; nt++) {
                    const int c = col0 + wn + nt * 8 + tg * 2;
                    *(unsigned int*)(C + c) = f22u(acc[mt][nt][half*2] * invz,
                                                   acc[mt][nt][half*2+1] * invz);
                }
            } else {  // KO
                const int tok = g_tok[z * CAPn + r];
                const float wt = g_wt[z * CAPn + r];
                const float* bp = bias + (size_t)e * Hn;
                const float* h2 = g_h2 + ((size_t)z * CAPn + r) * Hn;
                float* od = outp + (size_t)tok * Hn;
#pragma unroll
                for (int nt = 0; nt < 4; nt++) {
                    const int c = col0 + wn + nt * 8 + tg * 2;
                    float v0 = acc[mt][nt][half*2]   + bp[c]   + h2[c];
                    float v1 = acc[mt][nt][half*2+1] + bp[c+1] + h2[c+1];
                    atomicAdd(od + c,     wt * v0);
                    atomicAdd(od + c + 1, wt * v1);
                }
            }
        }
    }
}

// ---------------- launch: forked-stream graph (R15 + rowsum zeroing off L) ----------------
extern "C" void kernel_launch(void* const* d_in, const int* in_sizes, int n_in,
                              void* d_out, int out_size)
{
    const float* x    = (const float*)d_in[0];
    const float* Wg   = (const float*)d_in[1];
    const float* bg   = (const float*)d_in[2];
    const float* fc1w = (const float*)d_in[3];
    const float* fc1b = (const float*)d_in[4];
    const float* fc2w = (const float*)d_in[5];
    const float* fc2b = (const float*)d_in[6];
    const float* qw   = (const float*)d_in[7];
    const float* qb   = (const float*)d_in[8];
    const float* kw   = (const float*)d_in[9];
    const float* kb   = (const float*)d_in[10];
    const float* vw   = (const float*)d_in[11];
    const float* vb   = (const float*)d_in[12];
    const float* ow   = (const float*)d_in[13];
    const float* ob   = (const float*)d_in[14];
    float* out = (float*)d_out;

    __half* dxh;  cudaGetSymbolAddress((void**)&dxh,  g_xh);
    __half* dqwT; cudaGetSymbolAddress((void**)&dqwT, g_qwT);
    __half* dkwT; cudaGetSymbolAddress((void**)&dkwT, g_kwT);
    __half* dvwT; cudaGetSymbolAddress((void**)&dvwT, g_vwT);
    __half* dowT; cudaGetSymbolAddress((void**)&dowT, g_owT);
    __half* df1T; cudaGetSymbolAddress((void**)&df1T, g_f1T);
    __half* df2T; cudaGetSymbolAddress((void**)&df2T, g_f2T);
    float* drs;   cudaGetSymbolAddress((void**)&drs,  g_rowsum);

    // lazily created once (first call is the uncaptured correctness run)
    static cudaStream_t s1 = nullptr, s2 = nullptr, s3 = nullptr;
    static cudaEvent_t evStart, evBase, evH, evQT, evZ, evKK, evKV, evF2;
    if (s1 == nullptr) {
        cudaStreamCreateWithFlags(&s1, cudaStreamNonBlocking);
        cudaStreamCreateWithFlags(&s2, cudaStreamNonBlocking);
        cudaStreamCreateWithFlags(&s3, cudaStreamNonBlocking);
        cudaEventCreateWithFlags(&evStart, cudaEventDisableTiming);
        cudaEventCreateWithFlags(&evBase,  cudaEventDisableTiming);
        cudaEventCreateWithFlags(&evH,     cudaEventDisableTiming);
        cudaEventCreateWithFlags(&evQT,    cudaEventDisableTiming);
        cudaEventCreateWithFlags(&evZ,     cudaEventDisableTiming);
        cudaEventCreateWithFlags(&evKK,    cudaEventDisableTiming);
        cudaEventCreateWithFlags(&evKV,    cudaEventDisableTiming);
        cudaEventCreateWithFlags(&evF2,    cudaEventDisableTiming);
    }

    dim3 tb(32, 8);

    // ---- fork point ----
    cudaEventRecord(evStart, 0);
    cudaStreamWaitEvent(s1, evStart, 0);
    cudaStreamWaitEvent(s2, evStart, 0);
    cudaStreamWaitEvent(s3, evStart, 0);

    // s1: halve -> evH -> transpose kw -> KK (dense) -> evKK
    halve_kernel<<<(Tn * Hn / 4 + 255) / 256, 256, 0, s1>>>(x, dxh, Tn * Hn);
    cudaEventRecord(evH, s1);
    transpose_h_kernel<<<dim3(Hn / 32, Hn / 32, En), tb, 0, s1>>>(kw, dkwT, Hn, Hn);
    gemm_kernel<KK><<<dim3(Tn / 128, Hn / 128, En), 256, 0, s1>>>(kb, nullptr);
    cudaEventRecord(evKK, s1);

    // s2: zero out + zero rowsum -> evZ + vw,ow transpose -> [evH] KV (dense) -> evKV
    zero_kernel<<<(out_size + 255) / 256, 256, 0, s2>>>(out, out_size);
    zero_kernel<<<(NBUCK * CAPn + 255) / 256, 256, 0, s2>>>(drs, NBUCK * CAPn);
    cudaEventRecord(evZ, s2);
    transpose_h_kernel<<<dim3(Hn / 32, Hn / 32, En), tb, 0, s2>>>(vw, dvwT, Hn, Hn);
    transpose_h_kernel<<<dim3(Hn / 32, Hn / 32, En), tb, 0, s2>>>(ow, dowT, Hn, Hn);
    cudaStreamWaitEvent(s2, evH, 0);
    gemm_kernel<KV><<<dim3(Tn / 128, Hn / 128, En), 256, 0, s2>>>(vb, nullptr);
    cudaEventRecord(evKV, s2);

    // s3: qw transpose (off L) -> evQT -> f1,f2 transpose -> [evBase, evH] KF1 -> KF2 -> evF2
    transpose_h_kernel<<<dim3(Hn / 32, Hn / 32, En), tb, 0, s3>>>(qw, dqwT, Hn, Hn);
    cudaEventRecord(evQT, s3);
    transpose_h_kernel<<<dim3(Fn / 32, Hn / 32, En), tb, 0, s3>>>(fc1w, df1T, Hn, Fn);
    transpose_h_kernel<<<dim3(Hn / 32, Fn / 32, En), tb, 0, s3>>>(fc2w, df2T, Fn, Hn);

    // L: minimal reset + router (shortest serial prefix)
    reset_kernel<<<1, 32>>>();
    router_kernel<<<Tn / 8, 256>>>(x, Wg, bg);
    cudaEventRecord(evBase, 0);  // buckets ready

    cudaStreamWaitEvent(s3, evBase, 0);
    cudaStreamWaitEvent(s3, evH, 0);
    gemm_kernel<KF1><<<dim3(CAPn / 128, Fn / 128, NBUCK), 256, 0, s3>>>(fc1b, nullptr);
    gemm_kernel<KF2><<<dim3(CAPn / 128, Hn / 128, NBUCK), 256, 0, s3>>>(fc2b, nullptr);
    cudaEventRecord(evF2, s3);

    // L critical path: KQ -> KSC -> KPV -> KO
    cudaStreamWaitEvent(0, evH, 0);
    cudaStreamWaitEvent(0, evQT, 0);
    gemm_kernel<KQ><<<dim3(CAPn / 128, Hn / 128, NBUCK), 256>>>(qb, nullptr);
    cudaStreamWaitEvent(0, evKK, 0);
    cudaStreamWaitEvent(0, evZ, 0);
    gemm_kernel<KSC><<<dim3(CAPn / 128, Sn / 128, NBUCK), 256>>>(nullptr, nullptr);
    cudaStreamWaitEvent(0, evKV, 0);
    gemm_kernel<KPV><<<dim3(CAPn / 128, Hn / 128, NBUCK), 256>>>(nullptr, nullptr);
    cudaStreamWaitEvent(0, evF2, 0);
    gemm_kernel<KO><<<dim3(CAPn / 128, Hn / 128, NBUCK), 256>>>(ob, out);

    finalize_kernel<<<1, 32>>>(out, out_size);
}

// round 17
// speedup vs baseline: 1.0076x; 1.0076x over previous
#include <cuda_runtime.h>
#include <cuda_fp16.h>
#include <math.h>
#include <stdint.h>

// Problem constants
#define Bn 4
#define Sn 1024
#define Tn 4096          // Bn*Sn tokens
#define Hn 512
#define En 8
#define Fn 2048
#define NBUCK 32         // En*Bn  (expert, batch) buckets
#define CAPn 1024        // max tokens per bucket = Sn

// ---------------- scratch (__device__ globals; no allocation) ----------------
__device__ __half g_xh  [(size_t)Tn*Hn];
__device__ __half g_Kh  [(size_t)En*Tn*Hn];
__device__ __half g_Vth [(size_t)En*Hn*Tn];          // V TRANSPOSED [e][h][t]
__device__ __half g_qh  [(size_t)NBUCK*CAPn*Hn];
__device__ __half g_h1h [(size_t)NBUCK*CAPn*Fn];
__device__ __half g_atth[(size_t)NBUCK*CAPn*Sn];     // UNNORMALIZED exp(scores) fp16
__device__ __half g_ah  [(size_t)NBUCK*CAPn*Hn];
__device__ __half g_qwT[(size_t)En*Hn*Hn];
__device__ __half g_kwT[(size_t)En*Hn*Hn];
__device__ __half g_vwT[(size_t)En*Hn*Hn];
__device__ __half g_owT[(size_t)En*Hn*Hn];
__device__ __half g_f1T[(size_t)En*Fn*Hn];
__device__ __half g_f2T[(size_t)En*Hn*Fn];
__device__ float g_rowsum[(size_t)NBUCK*CAPn];       // softmax denominators
__device__ float g_h2[(size_t)NBUCK*CAPn*Hn];
__device__ int   g_cnt[NBUCK];
__device__ int   g_tok[NBUCK*CAPn];
__device__ float g_wt [NBUCK*CAPn];
__device__ float g_imp[En];

__device__ __forceinline__ unsigned int f22u(float a, float b) {
    __half2 h = __floats2half2_rn(a, b);
    return *(unsigned int*)&h;
}
__device__ __forceinline__ uint32_t smem_u32(const void* p) {
    uint32_t a;
    asm("{ .reg .u64 t; cvta.to.shared.u64 t, %1; cvt.u32.u64 %0, t; }" : "=r"(a) : "l"(p));
    return a;
}

// ---------------- small kernels ----------------
__global__ void reset_kernel() {
    int i = threadIdx.x;   // 1 block, 32 threads: only router prerequisites
    if (i < NBUCK) g_cnt[i] = 0;
    if (i < En)    g_imp[i] = 0.f;
}

__global__ void zero_kernel(float* __restrict__ out, int n) {
    int i = blockIdx.x * blockDim.x + threadIdx.x;
    if (i < n) out[i] = 0.f;
}

__global__ void halve_kernel(const float* __restrict__ src, __half* __restrict__ dst, int n) {
    int i = (blockIdx.x * blockDim.x + threadIdx.x) * 4;
    if (i < n) {
        float4 v = *(const float4*)(src + i);
        uint2 o = make_uint2(f22u(v.x, v.y), f22u(v.z, v.w));
        *(uint2*)(dst + i) = o;
    }
}

// fp32 [E][R][C] -> fp16 [E][C][R]
__global__ void transpose_h_kernel(const float* __restrict__ in, __half* __restrict__ out,
                                   int R, int C)
{
    __shared__ float t[32][33];
    int e = blockIdx.z;
    const float* src = in + (size_t)e * R * C;
    __half* dst = out + (size_t)e * R * C;
    int c0 = blockIdx.x * 32, r0 = blockIdx.y * 32;
    int x = threadIdx.x, y = threadIdx.y;   // (32, 8)
#pragma unroll
    for (int i = 0; i < 32; i += 8)
        t[y + i][x] = src[(size_t)(r0 + y + i) * C + c0 + x];
    __syncthreads();
#pragma unroll
    for (int i = 0; i < 32; i += 8)
        dst[(size_t)(c0 + y + i) * R + r0 + x] = __float2half_rn(t[x][y + i]);
}

// Router: one warp per token. Exact fp32. Also zeroes g_rowsum (8 entries/warp).
__global__ void router_kernel(const float* __restrict__ x,
                              const float* __restrict__ Wg,
                              const float* __restrict__ bg)
{
    int warp = (blockIdx.x * blockDim.x + threadIdx.x) >> 5;
    int lane = threadIdx.x & 31;
    if (warp >= Tn) return;
    const int t = warp;

    // fold rowsum zeroing into router: 4096 warps x 8 entries = 32768 = NBUCK*CAPn
    if (lane < 8) g_rowsum[warp * 8 + lane] = 0.f;

    float acc[En];
#pragma unroll
    for (int e = 0; e < En; e++) acc[e] = 0.f;

    for (int h = lane; h < Hn; h += 32) {
        float xv = x[(size_t)t * Hn + h];
        float4 w0 = *(const float4*)(Wg + (size_t)h * En);
        float4 w1 = *(const float4*)(Wg + (size_t)h * En + 4);
        acc[0] += xv * w0.x; acc[1] += xv * w0.y; acc[2] += xv * w0.z; acc[3] += xv * w0.w;
        acc[4] += xv * w1.x; acc[5] += xv * w1.y; acc[6] += xv * w1.z; acc[7] += xv * w1.w;
    }
#pragma unroll
    for (int off = 16; off > 0; off >>= 1) {
#pragma unroll
        for (int e = 0; e < En; e++)
            acc[e] += __shfl_xor_sync(0xffffffffu, acc[e], off);
    }
    if (lane != 0) return;

    float p[En];
    float m = -1e30f;
#pragma unroll
    for (int e = 0; e < En; e++) { p[e] = acc[e] + bg[e]; m = fmaxf(m, p[e]); }
    float s = 0.f;
#pragma unroll
    for (int e = 0; e < En; e++) { p[e] = expf(p[e] - m); s += p[e]; }
    float inv = 1.0f / s;
#pragma unroll
    for (int e = 0; e < En; e++) { p[e] *= inv; atomicAdd(&g_imp[e], p[e]); }

    int i1 = 0;
#pragma unroll
    for (int e = 1; e < En; e++) if (p[e] > p[i1]) i1 = e;
    int i2 = (i1 == 0) ? 1 : 0;
#pragma unroll
    for (int e = 0; e < En; e++) if (e != i1 && p[e] > p[i2]) i2 = e;

    float denom = p[i1] + p[i2];
    int b = t >> 10;
    int bk1 = i1 * Bn + b;
    int pos1 = atomicAdd(&g_cnt[bk1], 1);
    g_tok[bk1 * CAPn + pos1] = t;
    g_wt [bk1 * CAPn + pos1] = p[i1] / denom;
    int bk2 = i2 * Bn + b;
    int pos2 = atomicAdd(&g_cnt[bk2], 1);
    g_tok[bk2 * CAPn + pos2] = t;
    g_wt [bk2 * CAPn + pos2] = p[i2] / denom;
}

__global__ void finalize_kernel(float* __restrict__ out, int out_size)
{
    if (threadIdx.x == 0 && out_size > Tn * Hn) {
        float loss = 0.f;
        for (int e = 0; e < En; e++) {
            int a = 0;
            for (int b = 0; b < Bn; b++) a += g_cnt[e * Bn + b];
            loss += ((float)a / (float)Tn) * (g_imp[e] / (float)Tn);
        }
        out[Tn * Hn] = (float)En * loss;
    }
}

// ---------------- fp16 mma GEMM: 128x128 tile, 8 warps 64x32, 3-stage cp.async + ldmatrix ----------------
enum { KK = 0, KV = 1, KQ = 2, KF1 = 3, KF2 = 4, KSC = 5, KPV = 6, KO = 7 };

__device__ __forceinline__ void mma_f16_16x8x16(float* c, const unsigned int* a, const unsigned int* b) {
    asm volatile(
        "mma.sync.aligned.m16n8k16.row.col.f32.f16.f16.f32 "
        "{%0,%1,%2,%3}, {%4,%5,%6,%7}, {%8,%9}, {%0,%1,%2,%3};"
        : "+f"(c[0]), "+f"(c[1]), "+f"(c[2]), "+f"(c[3])
        : "r"(a[0]), "r"(a[1]), "r"(a[2]), "r"(a[3]), "r"(b[0]), "r"(b[1]));
}
#define LDSM4(r0, r1, r2, r3, addr) \
    asm volatile("ldmatrix.sync.aligned.m8n8.x4.shared.b16 {%0,%1,%2,%3}, [%4];" \
                 : "=r"(r0), "=r"(r1), "=r"(r2), "=r"(r3) : "r"(addr))
#define CP16(dst, src, sz) \
    asm volatile("cp.async.cg.shared.global [%0], [%1], 16, %2;" :: "r"(dst), "l"(src), "r"(sz) : "memory")
#define CP_COMMIT() asm volatile("cp.async.commit_group;" ::: "memory")
#define CP_WAIT(n)  asm volatile("cp.async.wait_group %0;" :: "n"(n) : "memory")

#define STR 24            // halfs per smem row (48 B) -> conflict-free LDSM & cp.async
#define TILEH (128*STR)   // halfs per tile (6 KB)

template <int KIND>
__global__ __launch_bounds__(256, 2)
void gemm_kernel(const float* __restrict__ bias, float* __restrict__ outp)
{
    constexpr bool BUCKET = (KIND != KK && KIND != KV);
    constexpr int  KDIM = (KIND == KF2) ? Fn : (KIND == KPV ? Sn : Hn);
    constexpr int  NC   = KDIM / 16;

    const int tid  = threadIdx.x;
    const int wid  = tid >> 5;
    const int lane = tid & 31;
    const int z = blockIdx.z;
    int e, bb = 0, M;
    if (BUCKET) {
        e = z >> 2; bb = z & 3;
        M = g_cnt[z];
        if ((int)(blockIdx.x * 128) >= M) return;
    } else {
        e = z; M = Tn;
    }

    const int row0 = blockIdx.x * 128;
    const int col0 = blockIdx.y * 128;

    const int lrow = tid & 127;
    const int s    = tid >> 7;
    const int grow = row0 + lrow;
    const bool aval = BUCKET ? (grow < M) : true;
    const unsigned avsz = aval ? 16u : 0u;

    const __half* aPtr = nullptr;
    if (aval) {
        if      (KIND == KK || KIND == KV)   aPtr = g_xh + (size_t)grow * Hn;
        else if (KIND == KQ || KIND == KF1)  aPtr = g_xh + (size_t)g_tok[z * CAPn + grow] * Hn;
        else if (KIND == KF2)                aPtr = g_h1h  + ((size_t)z * CAPn + grow) * Fn;
        else if (KIND == KSC)                aPtr = g_qh   + ((size_t)z * CAPn + grow) * Hn;
        else if (KIND == KPV)                aPtr = g_atth + ((size_t)z * CAPn + grow) * Sn;
        else                                 aPtr = g_ah   + ((size_t)z * CAPn + grow) * Hn;  // KO
        aPtr += s * 8;
    }
    const __half* bPtr;
    if      (KIND == KK)  bPtr = g_kwT + ((size_t)e * Hn + col0 + lrow) * Hn;
    else if (KIND == KV)  bPtr = g_vwT + ((size_t)e * Hn + col0 + lrow) * Hn;
    else if (KIND == KQ)  bPtr = g_qwT + ((size_t)e * Hn + col0 + lrow) * Hn;
    else if (KIND == KO)  bPtr = g_owT + ((size_t)e * Hn + col0 + lrow) * Hn;
    else if (KIND == KF1) bPtr = g_f1T + ((size_t)e * Fn + col0 + lrow) * Hn;
    else if (KIND == KF2) bPtr = g_f2T + ((size_t)e * Hn + col0 + lrow) * Fn;
    else if (KIND == KSC) bPtr = g_Kh  + ((size_t)e * Tn + (size_t)bb * Sn + col0 + lrow) * Hn;
    else                  bPtr = g_Vth + ((size_t)e * Hn + col0 + lrow) * Tn + bb * Sn;  // KPV
    bPtr += s * 8;

    __shared__ __align__(16) __half smh[6 * TILEH];   // 3 stages x (A,B) = 36 KB
    const uint32_t sb = smem_u32(smh);
    const uint32_t aDst = sb + (lrow * STR + s * 8) * 2;
    const uint32_t bDst = sb + 3 * TILEH * 2 + (lrow * STR + s * 8) * 2;

    float acc[4][4][4];
#pragma unroll
    for (int i = 0; i < 4; i++)
#pragma unroll
        for (int j = 0; j < 4; j++)
#pragma unroll
            for (int k = 0; k < 4; k++) acc[i][j][k] = 0.f;

    const int wm  = (wid >> 2) * 64;
    const int wn  = (wid & 3) * 32;
    const int grp = lane >> 2;
    const int tg  = lane & 3;

    const int arow = wm + (lane & 7) + ((lane >> 3) & 1) * 8;
    const int agr  = lane >> 4;
    const uint32_t aLd0 = sb + (arow * STR + agr * 8) * 2;
    const int brow = wn + (lane & 7) + ((lane >= 16) ? 8 : 0);
    const int bgr  = (lane >> 3) & 1;
    const uint32_t bLd0 = sb + 3 * TILEH * 2 + (brow * STR + bgr * 8) * 2;

    auto issue = [&](int st, int c) {
        CP16(aDst + st * TILEH * 2, aPtr + c * 16, avsz);
        CP16(bDst + st * TILEH * 2, bPtr + c * 16, 16u);
        CP_COMMIT();
    };

    issue(0, 0);
    issue(1, 1);

    for (int c = 0; c < NC; c++) {
        if (c + 1 < NC) { CP_WAIT(1); } else { CP_WAIT(0); }
        __syncthreads();
        if (c + 2 < NC) issue((c + 2) % 3, c + 2);

        const uint32_t off = ((c % 3) * TILEH) * 2;
        unsigned int af[4][4], bf[4][2];
#pragma unroll
        for (int mt = 0; mt < 4; mt++)
            LDSM4(af[mt][0], af[mt][1], af[mt][2], af[mt][3], aLd0 + off + mt * 16 * STR * 2);
        {
            unsigned int r0, r1, r2, r3;
            LDSM4(r0, r1, r2, r3, bLd0 + off);
            bf[0][0] = r0; bf[0][1] = r1; bf[1][0] = r2; bf[1][1] = r3;
            LDSM4(r0, r1, r2, r3, bLd0 + off + 16 * STR * 2);
            bf[2][0] = r0; bf[2][1] = r1; bf[3][0] = r2; bf[3][1] = r3;
        }
#pragma unroll
        for (int mt = 0; mt < 4; mt++)
#pragma unroll
            for (int nt = 0; nt < 4; nt++)
                mma_f16_16x8x16(acc[mt][nt], af[mt], bf[nt]);
    }

    // ---------------- epilogue ----------------
#pragma unroll
    for (int mt = 0; mt < 4; mt++) {
#pragma unroll
        for (int half = 0; half < 2; half++) {
            const int r = row0 + wm + mt * 16 + grp + half * 8;

            if (KIND == KSC) {
                // fused softmax part 1: exp + row-sum accumulation (shuffles kept convergent)
                const float scl = 0.044194173824159216f;  // 1/sqrt(512)
                float ev[8];
                float psum = 0.f;
#pragma unroll
                for (int nt = 0; nt < 4; nt++) {
                    ev[nt*2]   = __expf(acc[mt][nt][half*2]   * scl);
                    ev[nt*2+1] = __expf(acc[mt][nt][half*2+1] * scl);
                    psum += ev[nt*2] + ev[nt*2+1];
                }
                psum += __shfl_xor_sync(0xffffffffu, psum, 1);
                psum += __shfl_xor_sync(0xffffffffu, psum, 2);
                if (r < M) {
                    __half* C = g_atth + ((size_t)z * CAPn + r) * Sn;
#pragma unroll
                    for (int nt = 0; nt < 4; nt++) {
                        const int c = col0 + wn + nt * 8 + tg * 2;
                        *(unsigned int*)(C + c) = f22u(ev[nt*2], ev[nt*2+1]);
                    }
                    if (tg == 0) atomicAdd(&g_rowsum[z * CAPn + r], psum);
                }
                continue;
            }

            if (BUCKET && r >= M) continue;

            if (KIND == KK) {
                __half* C = g_Kh + ((size_t)e * Tn + r) * Hn;
                const float* bp = bias + (size_t)e * Hn;
#pragma unroll
                for (int nt = 0; nt < 4; nt++) {
                    const int c = col0 + wn + nt * 8 + tg * 2;
                    float2 bv = *(const float2*)(bp + c);
                    *(unsigned int*)(C + c) = f22u(acc[mt][nt][half*2] + bv.x,
                                                   acc[mt][nt][half*2+1] + bv.y);
                }
            } else if (KIND == KV) {
                const float* bp = bias + (size_t)e * Hn;
                __half* Vb = g_Vth + (size_t)e * Hn * Tn + r;
#pragma unroll
                for (int nt = 0; nt < 4; nt++) {
                    const int c = col0 + wn + nt * 8 + tg * 2;
                    float2 bv = *(const float2*)(bp + c);
                    Vb[(size_t)c * Tn]       = __float2half_rn(acc[mt][nt][half*2]   + bv.x);
                    Vb[(size_t)(c + 1) * Tn] = __float2half_rn(acc[mt][nt][half*2+1] + bv.y);
                }
            } else if (KIND == KQ) {
                __half* C = g_qh + ((size_t)z * CAPn + r) * Hn;
                const float* bp = bias + (size_t)e * Hn;
#pragma unroll
                for (int nt = 0; nt < 4; nt++) {
                    const int c = col0 + wn + nt * 8 + tg * 2;
                    float2 bv = *(const float2*)(bp + c);
                    *(unsigned int*)(C + c) = f22u(acc[mt][nt][half*2] + bv.x,
                                                   acc[mt][nt][half*2+1] + bv.y);
                }
            } else if (KIND == KF1) {
                __half* C = g_h1h + ((size_t)z * CAPn + r) * Fn;
                const float* bp = bias + (size_t)e * Fn;
#pragma unroll
                for (int nt = 0; nt < 4; nt++) {
                    const int c = col0 + wn + nt * 8 + tg * 2;
                    float2 bv = *(const float2*)(bp + c);
                    float t0 = acc[mt][nt][half*2]   + bv.x;
                    float t1 = acc[mt][nt][half*2+1] + bv.y;
                    t0 = 0.5f * t0 * (1.0f + erff(t0 * 0.70710678118654752f));
                    t1 = 0.5f * t1 * (1.0f + erff(t1 * 0.70710678118654752f));
                    *(unsigned int*)(C + c) = f22u(t0, t1);
                }
            } else if (KIND == KF2) {
                float* C = g_h2 + ((size_t)z * CAPn + r) * Hn;
                const float* bp = bias + (size_t)e * Hn;
#pragma unroll
                for (int nt = 0; nt < 4; nt++) {
                    const int c = col0 + wn + nt * 8 + tg * 2;
                    float2 bv = *(const float2*)(bp + c);
                    float2 v = make_float2(acc[mt][nt][half*2]   + bv.x,
                                           acc[mt][nt][half*2+1] + bv.y);
                    *(float2*)(C + c) = v;
                }
            } else if (KIND == KPV) {
                // fused softmax part 2: scale by 1/rowsum
                const float invz = 1.0f / g_rowsum[z * CAPn + r];
                __half* C = g_ah + ((size_t)z * CAPn + r) * Hn;
#pragma unroll
                for (int nt = 0; nt < 4; nt++) {
                    const int c = col0 + wn + nt * 8 + tg * 2;
                    *(unsigned int*)(C + c) = f22u(acc[mt][nt][half*2] * invz,
                                                   acc[mt][nt][half*2+1] * invz);
                }
            } else {  // KO
                const int tok = g_tok[z * CAPn + r];
                const float wt = g_wt[z * CAPn + r];
                const float* bp = bias + (size_t)e * Hn;
                const float* h2 = g_h2 + ((size_t)z * CAPn + r) * Hn;
                float* od = outp + (size_t)tok * Hn;
#pragma unroll
                for (int nt = 0; nt < 4; nt++) {
                    const int c = col0 + wn + nt * 8 + tg * 2;
                    float v0 = acc[mt][nt][half*2]   + bp[c]   + h2[c];
                    float v1 = acc[mt][nt][half*2+1] + bp[c+1] + h2[c+1];
                    atomicAdd(od + c,     wt * v0);
                    atomicAdd(od + c + 1, wt * v1);
                }
            }
        }
    }
}

// ---------------- launch: forked-stream graph (R15 + rowsum zeroing folded into router) ----------------
extern "C" void kernel_launch(void* const* d_in, const int* in_sizes, int n_in,
                              void* d_out, int out_size)
{
    const float* x    = (const float*)d_in[0];
    const float* Wg   = (const float*)d_in[1];
    const float* bg   = (const float*)d_in[2];
    const float* fc1w = (const float*)d_in[3];
    const float* fc1b = (const float*)d_in[4];
    const float* fc2w = (const float*)d_in[5];
    const float* fc2b = (const float*)d_in[6];
    const float* qw   = (const float*)d_in[7];
    const float* qb   = (const float*)d_in[8];
    const float* kw   = (const float*)d_in[9];
    const float* kb   = (const float*)d_in[10];
    const float* vw   = (const float*)d_in[11];
    const float* vb   = (const float*)d_in[12];
    const float* ow   = (const float*)d_in[13];
    const float* ob   = (const float*)d_in[14];
    float* out = (float*)d_out;

    __half* dxh;  cudaGetSymbolAddress((void**)&dxh,  g_xh);
    __half* dqwT; cudaGetSymbolAddress((void**)&dqwT, g_qwT);
    __half* dkwT; cudaGetSymbolAddress((void**)&dkwT, g_kwT);
    __half* dvwT; cudaGetSymbolAddress((void**)&dvwT, g_vwT);
    __half* dowT; cudaGetSymbolAddress((void**)&dowT, g_owT);
    __half* df1T; cudaGetSymbolAddress((void**)&df1T, g_f1T);
    __half* df2T; cudaGetSymbolAddress((void**)&df2T, g_f2T);

    // lazily created once (first call is the uncaptured correctness run)
    static cudaStream_t s1 = nullptr, s2 = nullptr, s3 = nullptr;
    static cudaEvent_t evStart, evBase, evH, evQT, evKK, evKV, evF2;
    if (s1 == nullptr) {
        cudaStreamCreateWithFlags(&s1, cudaStreamNonBlocking);
        cudaStreamCreateWithFlags(&s2, cudaStreamNonBlocking);
        cudaStreamCreateWithFlags(&s3, cudaStreamNonBlocking);
        cudaEventCreateWithFlags(&evStart, cudaEventDisableTiming);
        cudaEventCreateWithFlags(&evBase,  cudaEventDisableTiming);
        cudaEventCreateWithFlags(&evH,     cudaEventDisableTiming);
        cudaEventCreateWithFlags(&evQT,    cudaEventDisableTiming);
        cudaEventCreateWithFlags(&evKK,    cudaEventDisableTiming);
        cudaEventCreateWithFlags(&evKV,    cudaEventDisableTiming);
        cudaEventCreateWithFlags(&evF2,    cudaEventDisableTiming);
    }

    dim3 tb(32, 8);

    // ---- fork point ----
    cudaEventRecord(evStart, 0);
    cudaStreamWaitEvent(s1, evStart, 0);
    cudaStreamWaitEvent(s2, evStart, 0);
    cudaStreamWaitEvent(s3, evStart, 0);

    // s1: halve -> evH -> transpose kw -> KK (dense) -> evKK
    halve_kernel<<<(Tn * Hn / 4 + 255) / 256, 256, 0, s1>>>(x, dxh, Tn * Hn);
    cudaEventRecord(evH, s1);
    transpose_h_kernel<<<dim3(Hn / 32, Hn / 32, En), tb, 0, s1>>>(kw, dkwT, Hn, Hn);
    gemm_kernel<KK><<<dim3(Tn / 128, Hn / 128, En), 256, 0, s1>>>(kb, nullptr);
    cudaEventRecord(evKK, s1);

    // s2: zero out + vw,ow transpose -> [evH] KV (dense) -> evKV
    zero_kernel<<<(out_size + 255) / 256, 256, 0, s2>>>(out, out_size);
    transpose_h_kernel<<<dim3(Hn / 32, Hn / 32, En), tb, 0, s2>>>(vw, dvwT, Hn, Hn);
    transpose_h_kernel<<<dim3(Hn / 32, Hn / 32, En), tb, 0, s2>>>(ow, dowT, Hn, Hn);
    cudaStreamWaitEvent(s2, evH, 0);
    gemm_kernel<KV><<<dim3(Tn / 128, Hn / 128, En), 256, 0, s2>>>(vb, nullptr);
    cudaEventRecord(evKV, s2);

    // s3: qw transpose (off L) -> evQT -> f1,f2 transpose -> [evBase, evH] KF1 -> KF2 -> evF2
    transpose_h_kernel<<<dim3(Hn / 32, Hn / 32, En), tb, 0, s3>>>(qw, dqwT, Hn, Hn);
    cudaEventRecord(evQT, s3);
    transpose_h_kernel<<<dim3(Fn / 32, Hn / 32, En), tb, 0, s3>>>(fc1w, df1T, Hn, Fn);
    transpose_h_kernel<<<dim3(Hn / 32, Fn / 32, En), tb, 0, s3>>>(fc2w, df2T, Fn, Hn);

    // L: minimal reset + router (rowsum zeroing now inside router)
    reset_kernel<<<1, 32>>>();
    router_kernel<<<Tn / 8, 256>>>(x, Wg, bg);
    cudaEventRecord(evBase, 0);  // buckets + rowsum ready

    cudaStreamWaitEvent(s3, evBase, 0);
    cudaStreamWaitEvent(s3, evH, 0);
    gemm_kernel<KF1><<<dim3(CAPn / 128, Fn / 128, NBUCK), 256, 0, s3>>>(fc1b, nullptr);
    gemm_kernel<KF2><<<dim3(CAPn / 128, Hn / 128, NBUCK), 256, 0, s3>>>(fc2b, nullptr);
    cudaEventRecord(evF2, s3);

    // L critical path: KQ -> KSC -> KPV -> KO
    cudaStreamWaitEvent(0, evH, 0);
    cudaStreamWaitEvent(0, evQT, 0);
    gemm_kernel<KQ><<<dim3(CAPn / 128, Hn / 128, NBUCK), 256>>>(qb, nullptr);
    cudaStreamWaitEvent(0, evKK, 0);
    gemm_kernel<KSC><<<dim3(CAPn / 128, Sn / 128, NBUCK), 256>>>(nullptr, nullptr);
    cudaStreamWaitEvent(0, evKV, 0);
    gemm_kernel<KPV><<<dim3(CAPn / 128, Hn / 128, NBUCK), 256>>>(nullptr, nullptr);
    cudaStreamWaitEvent(0, evF2, 0);
    gemm_kernel<KO><<<dim3(CAPn / 128, Hn / 128, NBUCK), 256>>>(ob, out);

    finalize_kernel<<<1, 32>>>(out, out_size);
}